// round 9
// baseline (speedup 1.0000x reference)
#include <cuda_runtime.h>
#include <cuda_bf16.h>
#include <cstdint>

// ============================================================
// Swin window attention pipeline, R9:
//   gemm: 512-thr CTA, warp tile 32x32, 3-stage ring,
//         ONE barrier per K-chunk, ldmatrix fragments
//   0) split x -> bf16 hi/lo ; split+transpose weights
//   1) qkv = x @ w_qkv + b_qkv   (mma.sync, 3-term split)
//   2) windowed attention (fp32) -> O hi/lo (bf16)
//   3) out = O @ w_out + b_out
// ============================================================

#define M_TOTAL 200704          // 64*56*56 = 1568 * 128
typedef unsigned long long u64;

// ---------------- device scratch ----------------
__device__ float g_qkv[(size_t)M_TOTAL * 768];              // 616 MB
__device__ __nv_bfloat16 g_x_hi[(size_t)M_TOTAL * 256];
__device__ __nv_bfloat16 g_x_lo[(size_t)M_TOTAL * 256];
__device__ __nv_bfloat16 g_o_hi[(size_t)M_TOTAL * 256];
__device__ __nv_bfloat16 g_o_lo[(size_t)M_TOTAL * 256];
__device__ __nv_bfloat16 g_wq_hi[768 * 256];
__device__ __nv_bfloat16 g_wq_lo[768 * 256];
__device__ __nv_bfloat16 g_wo_hi[256 * 256];
__device__ __nv_bfloat16 g_wo_lo[256 * 256];

// ---------------- helpers ----------------
__device__ __forceinline__ uint32_t smem_u32(const void* p) {
    uint32_t a;
    asm("{ .reg .u64 t; cvta.to.shared.u64 t, %1; cvt.u32.u64 %0, t; }" : "=r"(a) : "l"(p));
    return a;
}
__device__ __forceinline__ void cpasync16(uint32_t dst, const void* src) {
    asm volatile("cp.async.cg.shared.global [%0], [%1], 16;" :: "r"(dst), "l"(src) : "memory");
}
#define CP_COMMIT() asm volatile("cp.async.commit_group;" ::: "memory")
#define CP_WAIT1()  asm volatile("cp.async.wait_group 1;" ::: "memory")

__device__ __forceinline__ void ldsm_x4(uint32_t* r, uint32_t addr) {
    asm volatile("ldmatrix.sync.aligned.m8n8.x4.shared.b16 {%0,%1,%2,%3}, [%4];"
        : "=r"(r[0]), "=r"(r[1]), "=r"(r[2]), "=r"(r[3]) : "r"(addr));
}

__device__ __forceinline__ void split1(float a, uint16_t& h, uint16_t& l) {
    __nv_bfloat16 hb = __float2bfloat16_rn(a);
    float hf = __bfloat162float(hb);
    __nv_bfloat16 lb = __float2bfloat16_rn(a - hf);
    h = __bfloat16_as_ushort(hb);
    l = __bfloat16_as_ushort(lb);
}

__device__ __forceinline__ void mma16816(float* c, const uint32_t* a, uint32_t b0, uint32_t b1) {
    asm volatile("mma.sync.aligned.m16n8k16.row.col.f32.bf16.bf16.f32 "
        "{%0,%1,%2,%3}, {%4,%5,%6,%7}, {%8,%9}, {%0,%1,%2,%3};"
        : "+f"(c[0]), "+f"(c[1]), "+f"(c[2]), "+f"(c[3])
        : "r"(a[0]), "r"(a[1]), "r"(a[2]), "r"(a[3]), "r"(b0), "r"(b1));
}

// ---------------- prep kernels ----------------
__global__ void prep_x(const float* __restrict__ x) {
    size_t i = ((size_t)blockIdx.x * 256 + threadIdx.x) * 8;
    float4 a0 = *(const float4*)(x + i);
    float4 a1 = *(const float4*)(x + i + 4);
    uint16_t h[8], l[8];
    split1(a0.x, h[0], l[0]); split1(a0.y, h[1], l[1]);
    split1(a0.z, h[2], l[2]); split1(a0.w, h[3], l[3]);
    split1(a1.x, h[4], l[4]); split1(a1.y, h[5], l[5]);
    split1(a1.z, h[6], l[6]); split1(a1.w, h[7], l[7]);
    uint4 hw, lw;
    hw.x = h[0] | ((uint32_t)h[1] << 16); hw.y = h[2] | ((uint32_t)h[3] << 16);
    hw.z = h[4] | ((uint32_t)h[5] << 16); hw.w = h[6] | ((uint32_t)h[7] << 16);
    lw.x = l[0] | ((uint32_t)l[1] << 16); lw.y = l[2] | ((uint32_t)l[3] << 16);
    lw.z = l[4] | ((uint32_t)l[5] << 16); lw.w = l[6] | ((uint32_t)l[7] << 16);
    *(uint4*)(g_x_hi + i) = hw;
    *(uint4*)(g_x_lo + i) = lw;
}
__global__ void prep_wqkv(const float* __restrict__ w) {
    int k = blockIdx.x;          // 0..255
    int n = threadIdx.x;         // 0..767
    uint16_t h, l;
    split1(w[k * 768 + n], h, l);
    g_wq_hi[n * 256 + k] = __ushort_as_bfloat16(h);
    g_wq_lo[n * 256 + k] = __ushort_as_bfloat16(l);
}
__global__ void prep_wout(const float* __restrict__ w) {
    int k = blockIdx.x;          // 0..255
    int n = threadIdx.x;         // 0..255
    uint16_t h, l;
    split1(w[k * 256 + n], h, l);
    g_wo_hi[n * 256 + k] = __ushort_as_bfloat16(h);
    g_wo_lo[n * 256 + k] = __ushort_as_bfloat16(l);
}

// ---------------- pipelined split-bf16 GEMM via mma.sync ----------------
// C[Mt,Nt] = Ahi/lo[Mt,256] @ (Whi/lo[Nt,256])^T + bias
// CTA tile 128x128, 16 warps (warp tile 32x32), K chunks of 32,
// 3-stage ring, ONE barrier per chunk, ldmatrix.x4 fragments.

#define LDA 40                        // bf16 stride: 8-row x 16B phases conflict-free
#define ARR_B (128 * LDA * 2)         // 10240 bytes per array (incl pad)
#define STG_B (4 * ARR_B)             // 40960 bytes per stage
#define OFF_AHI 0
#define OFF_ALO ARR_B
#define OFF_BHI (2 * ARR_B)
#define OFF_BLO (3 * ARR_B)
#define SMO_BIAS (3 * STG_B)          // 122880
#define SMO_TOTAL (SMO_BIAS + 512)    // 123392

__global__ __launch_bounds__(512, 1)
void gemm_mma(const __nv_bfloat16* __restrict__ Ahi,
              const __nv_bfloat16* __restrict__ Alo,
              const __nv_bfloat16* __restrict__ Bhi,
              const __nv_bfloat16* __restrict__ Blo,
              const float* __restrict__ bias,
              float* __restrict__ C,
              int Ntotal, int nN)
{
    extern __shared__ char smem[];
    float* sBias = (float*)(smem + SMO_BIAS);
    const uint32_t sb = smem_u32(smem);

    const int tid = threadIdx.x;
    const int m0 = (blockIdx.x / nN) * 128;
    const int n0 = (blockIdx.x % nN) * 128;
    const int wid = tid >> 5, lane = tid & 31;
    const int wm = wid & 3, wn = wid >> 2;      // 4 x 4 warp grid
    const int g = lane >> 2, tig = lane & 3;

    if (tid < 128) sBias[tid] = bias[n0 + tid];

    // staging coords: row = tid>>2, 16B unit = tid&3  (1 unit per array per chunk)
    const int sr = tid >> 2;
    const int su = tid & 3;
    const size_t goA = (size_t)(m0 + sr) * 256 + su * 8;
    const size_t goB = (size_t)(n0 + sr) * 256 + su * 8;
    const uint32_t so = (uint32_t)(sr * LDA + su * 8) * 2;

    // ldmatrix lane address components
    const int lane15 = lane & 15;
    const int acol8 = (lane >> 4) * 8;                       // A: col +8 for lanes 16-31
    const uint32_t aoff = (uint32_t)((wm * 32 + lane15) * LDA + acol8) * 2;
    const int brow = (lane & 7) + ((lane & 16) ? 8 : 0);     // B: row within nf-pair
    const int bcol8 = (lane & 8) ? 8 : 0;
    const uint32_t boff = (uint32_t)((wn * 32 + brow) * LDA + bcol8) * 2;

    float c[2][4][4];
    #pragma unroll
    for (int mf = 0; mf < 2; mf++)
        #pragma unroll
        for (int nf = 0; nf < 4; nf++)
            #pragma unroll
            for (int j = 0; j < 4; j++) c[mf][nf][j] = 0.f;

    // ---- prologue: load chunks 0,1 into slots 0,1 ----
    #pragma unroll
    for (int pc = 0; pc < 2; pc++) {
        uint32_t st = sb + pc * STG_B + so;
        size_t ko = (size_t)pc * 32;
        cpasync16(st + OFF_AHI, Ahi + goA + ko);
        cpasync16(st + OFF_ALO, Alo + goA + ko);
        cpasync16(st + OFF_BHI, Bhi + goB + ko);
        cpasync16(st + OFF_BLO, Blo + goB + ko);
        CP_COMMIT();
    }

    #pragma unroll 1
    for (int kc = 0; kc < 8; kc++) {
        CP_WAIT1();            // chunk kc resident (groups complete in commit order)
        __syncthreads();       // everyone sees chunk kc; slot (kc+2)%3 readers all done

        // issue chunk kc+2 into ring slot (kc+2)%3
        if (kc + 2 < 8) {
            uint32_t st = sb + ((kc + 2) % 3) * STG_B + so;
            size_t ko = (size_t)(kc + 2) * 32;
            cpasync16(st + OFF_AHI, Ahi + goA + ko);
            cpasync16(st + OFF_ALO, Alo + goA + ko);
            cpasync16(st + OFF_BHI, Bhi + goB + ko);
            cpasync16(st + OFF_BLO, Blo + goB + ko);
        }
        CP_COMMIT();           // unconditional: keeps group positions aligned

        // ---- compute chunk kc ----
        const uint32_t stg = sb + (kc % 3) * STG_B;
        #pragma unroll
        for (int ks = 0; ks < 2; ks++) {
            const uint32_t ksb = stg + ks * 32;     // ks*16 cols * 2B
            uint32_t ah[2][4], al[2][4];
            #pragma unroll
            for (int mf = 0; mf < 2; mf++) {
                uint32_t aa = ksb + aoff + mf * (16 * LDA * 2);
                ldsm_x4(ah[mf], aa + OFF_AHI);
                ldsm_x4(al[mf], aa + OFF_ALO);
            }
            #pragma unroll
            for (int nfp = 0; nfp < 2; nfp++) {
                uint32_t ba = ksb + boff + nfp * (16 * LDA * 2);
                uint32_t bh[4], bl[4];
                ldsm_x4(bh, ba + OFF_BHI);
                ldsm_x4(bl, ba + OFF_BLO);
                #pragma unroll
                for (int mf = 0; mf < 2; mf++) {
                    mma16816(c[mf][2 * nfp],     ah[mf], bh[0], bh[1]);
                    mma16816(c[mf][2 * nfp],     ah[mf], bl[0], bl[1]);
                    mma16816(c[mf][2 * nfp],     al[mf], bh[0], bh[1]);
                    mma16816(c[mf][2 * nfp + 1], ah[mf], bh[2], bh[3]);
                    mma16816(c[mf][2 * nfp + 1], ah[mf], bl[2], bl[3]);
                    mma16816(c[mf][2 * nfp + 1], al[mf], bh[2], bh[3]);
                }
            }
        }
    }

    // ---- epilogue ----
    #pragma unroll
    for (int mf = 0; mf < 2; mf++) {
        int row0 = m0 + wm * 32 + mf * 16 + g;
        #pragma unroll
        for (int nf = 0; nf < 4; nf++) {
            int cl = wn * 32 + nf * 8 + tig * 2;
            float bx = sBias[cl], by = sBias[cl + 1];
            float2 v0 = make_float2(c[mf][nf][0] + bx, c[mf][nf][1] + by);
            float2 v1 = make_float2(c[mf][nf][2] + bx, c[mf][nf][3] + by);
            *(float2*)(C + (size_t)row0 * Ntotal + n0 + cl) = v0;
            *(float2*)(C + (size_t)(row0 + 8) * Ntotal + n0 + cl) = v1;
        }
    }
}

// ---------------- windowed attention (fp32) ----------------
#define AQS 34
#define AKT 52
#define ASS 50

__device__ __forceinline__ u64 splat2(float a) {
    u64 r; asm("mov.b64 %0, {%1, %1};" : "=l"(r) : "f"(a)); return r;
}
__device__ __forceinline__ float2 unpack2(u64 v) {
    float2 f; asm("mov.b64 {%0, %1}, %2;" : "=f"(f.x), "=f"(f.y) : "l"(v)); return f;
}
#define FMA2(d, a, b) asm("fma.rn.f32x2 %0, %1, %2, %0;" : "+l"(d) : "l"(a), "l"(b))

__global__ __launch_bounds__(256)
void attn_kernel(const float* __restrict__ qkv,
                 const float* __restrict__ pos,
                 __nv_bfloat16* __restrict__ Ohi,
                 __nv_bfloat16* __restrict__ Olo)
{
    __shared__ float Q[52 * AQS];
    __shared__ float KT[32 * AKT];
    __shared__ float V[49 * AQS];
    __shared__ float S[49 * ASS];
    __shared__ float POS[170];

    const int tid = threadIdx.x;
    const int win = blockIdx.x;
    const int b = win >> 6, wh = (win >> 3) & 7, ww = win & 7;
    const int ty = tid >> 4, tx = tid & 15;
    const int ty4 = ty * 4, dx = tx * 2;
    const float scl = 5.656854249492381f;   // sqrt(32)

    for (int i = tid; i < 169; i += 256) POS[i] = pos[i];
    const int rowbase = (b * 56 + wh * 7) * 56 + ww * 7;

    for (int h = 0; h < 8; h++) {
        __syncthreads();
        for (int q = tid; q < 784; q += 256) {
            int t = q >> 4, d2 = (q & 15) << 1;
            long row = rowbase + (t / 7) * 56 + (t % 7);
            const float* p = qkv + row * 768 + h * 32 + d2;
            float2 qv = *(const float2*)p;
            float2 kv = *(const float2*)(p + 256);
            float2 vv = *(const float2*)(p + 512);
            *(float2*)(Q + t * AQS + d2) = qv;
            KT[d2 * AKT + t] = kv.x;
            KT[(d2 + 1) * AKT + t] = kv.y;
            *(float2*)(V + t * AQS + d2) = vv;
        }
        __syncthreads();

        if (tid < 169) {
            int sy = tid / 13, sx = tid - sy * 13;
            int r0 = 4 * sy, c0 = 4 * sx;
            u64 sa[4][2];
            #pragma unroll
            for (int i = 0; i < 4; i++) { sa[i][0] = 0ULL; sa[i][1] = 0ULL; }
            #pragma unroll 4
            for (int d = 0; d < 32; d += 2) {
                u64 k0a = *(const u64*)(KT + d * AKT + c0);
                u64 k0b = *(const u64*)(KT + d * AKT + c0 + 2);
                u64 k1a = *(const u64*)(KT + (d + 1) * AKT + c0);
                u64 k1b = *(const u64*)(KT + (d + 1) * AKT + c0 + 2);
                #pragma unroll
                for (int i = 0; i < 4; i++) {
                    float2 qv = *(const float2*)(Q + (r0 + i) * AQS + d);
                    u64 qx = splat2(qv.x), qy = splat2(qv.y);
                    FMA2(sa[i][0], qx, k0a);
                    FMA2(sa[i][1], qx, k0b);
                    FMA2(sa[i][0], qy, k1a);
                    FMA2(sa[i][1], qy, k1b);
                }
            }
            #pragma unroll
            for (int i = 0; i < 4; i++) {
                int r = r0 + i;
                if (r < 49) {
                    int br = r / 7 + r % 7;
                    #pragma unroll
                    for (int jc = 0; jc < 2; jc++) {
                        int cc = c0 + 2 * jc;
                        if (cc <= 48) {
                            float2 f = unpack2(sa[i][jc]);
                            int bc0 = cc / 7 + cc % 7;
                            int bc1 = (cc + 1) / 7 + (cc + 1) % 7;
                            f.x = f.x * scl + POS[br * 13 + bc0];
                            f.y = f.y * scl + POS[br * 13 + bc1];
                            *(float2*)(S + r * ASS + cc) = f;
                        }
                    }
                }
            }
        }
        __syncthreads();

        {
            int warp = tid >> 5, lane = tid & 31;
            for (int r = warp; r < 49; r += 8) {
                float v0 = S[r * ASS + lane];
                float v1 = (lane + 32 < 49) ? S[r * ASS + lane + 32] : -3.0e38f;
                float m = fmaxf(v0, v1);
                #pragma unroll
                for (int off = 16; off > 0; off >>= 1)
                    m = fmaxf(m, __shfl_xor_sync(0xffffffffu, m, off));
                float e0 = __expf(v0 - m);
                float e1 = (lane + 32 < 49) ? __expf(v1 - m) : 0.f;
                float ss = e0 + e1;
                #pragma unroll
                for (int off = 16; off > 0; off >>= 1)
                    ss += __shfl_xor_sync(0xffffffffu, ss, off);
                float inv = 1.f / ss;
                S[r * ASS + lane] = e0 * inv;
                if (lane + 32 < 49) S[r * ASS + lane + 32] = e1 * inv;
            }
        }
        __syncthreads();

        {
            int rr[4];
            #pragma unroll
            for (int i = 0; i < 4; i++) rr[i] = (ty4 + i < 49) ? (ty4 + i) : 0;
            u64 o[4] = {0ULL, 0ULL, 0ULL, 0ULL};
            #pragma unroll 4
            for (int l = 0; l < 48; l += 2) {
                u64 v0 = *(const u64*)(V + l * AQS + dx);
                u64 v1 = *(const u64*)(V + (l + 1) * AQS + dx);
                #pragma unroll
                for (int i = 0; i < 4; i++) {
                    float2 sv = *(const float2*)(S + rr[i] * ASS + l);
                    FMA2(o[i], splat2(sv.x), v0);
                    FMA2(o[i], splat2(sv.y), v1);
                }
            }
            {
                u64 v48 = *(const u64*)(V + 48 * AQS + dx);
                #pragma unroll
                for (int i = 0; i < 4; i++)
                    FMA2(o[i], splat2(S[rr[i] * ASS + 48]), v48);
            }
            #pragma unroll
            for (int i = 0; i < 4; i++) {
                int row = ty4 + i;
                if (row < 49) {
                    long gr = rowbase + (row / 7) * 56 + (row % 7);
                    float2 v = unpack2(o[i]);
                    uint16_t h0, l0, h1, l1;
                    split1(v.x, h0, l0);
                    split1(v.y, h1, l1);
                    *(uint32_t*)(Ohi + gr * 256 + h * 32 + dx) = (uint32_t)h0 | ((uint32_t)h1 << 16);
                    *(uint32_t*)(Olo + gr * 256 + h * 32 + dx) = (uint32_t)l0 | ((uint32_t)l1 << 16);
                }
            }
        }
    }
}

// ---------------- host launcher ----------------
extern "C" void kernel_launch(void* const* d_in, const int* in_sizes, int n_in,
                              void* d_out, int out_size)
{
    const float* x    = (const float*)d_in[0];
    const float* pos  = (const float*)d_in[1];
    const float* wqkv = (const float*)d_in[2];
    const float* bqkv = (const float*)d_in[3];
    const float* wout = (const float*)d_in[4];
    const float* bout = (const float*)d_in[5];
    float* out = (float*)d_out;

    void *p_qkv, *p_xh, *p_xl, *p_oh, *p_ol, *p_wqh, *p_wql, *p_woh, *p_wol;
    cudaGetSymbolAddress(&p_qkv, g_qkv);
    cudaGetSymbolAddress(&p_xh, g_x_hi);
    cudaGetSymbolAddress(&p_xl, g_x_lo);
    cudaGetSymbolAddress(&p_oh, g_o_hi);
    cudaGetSymbolAddress(&p_ol, g_o_lo);
    cudaGetSymbolAddress(&p_wqh, g_wq_hi);
    cudaGetSymbolAddress(&p_wql, g_wq_lo);
    cudaGetSymbolAddress(&p_woh, g_wo_hi);
    cudaGetSymbolAddress(&p_wol, g_wo_lo);

    cudaFuncSetAttribute(gemm_mma, cudaFuncAttributeMaxDynamicSharedMemorySize, SMO_TOTAL);

    prep_x<<<M_TOTAL * 256 / (256 * 8), 256>>>(x);
    prep_wqkv<<<256, 768>>>(wqkv);
    prep_wout<<<256, 256>>>(wout);

    // GEMM1: qkv = x @ w_qkv + b_qkv   (M=200704, N=768)
    gemm_mma<<<(M_TOTAL / 128) * 6, 512, SMO_TOTAL>>>(
        (const __nv_bfloat16*)p_xh, (const __nv_bfloat16*)p_xl,
        (const __nv_bfloat16*)p_wqh, (const __nv_bfloat16*)p_wql,
        bqkv, (float*)p_qkv, 768, 6);

    // windowed attention
    attn_kernel<<<4096, 256>>>((const float*)p_qkv, pos,
                               (__nv_bfloat16*)p_oh, (__nv_bfloat16*)p_ol);

    // GEMM2: out = O @ w_out + b_out (M=200704, N=256)
    gemm_mma<<<(M_TOTAL / 128) * 2, 512, SMO_TOTAL>>>(
        (const __nv_bfloat16*)p_oh, (const __nv_bfloat16*)p_ol,
        (const __nv_bfloat16*)p_woh, (const __nv_bfloat16*)p_wol,
        bout, out, 256, 2);
}

// round 10
// speedup vs baseline: 1.0895x; 1.0895x over previous
#include <cuda_runtime.h>
#include <cuda_bf16.h>
#include <cstdint>

// ============================================================
// Swin window attention pipeline, R10:
//   gemm: CTA tile 128x256, 512 thr (4x4 warps, tile 32x64),
//         3-stage ring, ONE barrier per K-chunk, ldmatrix
//   0) split x -> bf16 hi/lo ; split+transpose weights
//   1) qkv = x @ w_qkv + b_qkv   (mma.sync, 3-term split)
//   2) windowed attention (fp32) -> O hi/lo (bf16)
//   3) out = O @ w_out + b_out
// ============================================================

#define M_TOTAL 200704          // 64*56*56 = 1568 * 128
typedef unsigned long long u64;

// ---------------- device scratch ----------------
__device__ float g_qkv[(size_t)M_TOTAL * 768];              // 616 MB
__device__ __nv_bfloat16 g_x_hi[(size_t)M_TOTAL * 256];
__device__ __nv_bfloat16 g_x_lo[(size_t)M_TOTAL * 256];
__device__ __nv_bfloat16 g_o_hi[(size_t)M_TOTAL * 256];
__device__ __nv_bfloat16 g_o_lo[(size_t)M_TOTAL * 256];
__device__ __nv_bfloat16 g_wq_hi[768 * 256];
__device__ __nv_bfloat16 g_wq_lo[768 * 256];
__device__ __nv_bfloat16 g_wo_hi[256 * 256];
__device__ __nv_bfloat16 g_wo_lo[256 * 256];

// ---------------- helpers ----------------
__device__ __forceinline__ uint32_t smem_u32(const void* p) {
    uint32_t a;
    asm("{ .reg .u64 t; cvta.to.shared.u64 t, %1; cvt.u32.u64 %0, t; }" : "=r"(a) : "l"(p));
    return a;
}
__device__ __forceinline__ void cpasync16(uint32_t dst, const void* src) {
    asm volatile("cp.async.cg.shared.global [%0], [%1], 16;" :: "r"(dst), "l"(src) : "memory");
}
#define CP_COMMIT() asm volatile("cp.async.commit_group;" ::: "memory")
#define CP_WAIT1()  asm volatile("cp.async.wait_group 1;" ::: "memory")

__device__ __forceinline__ void ldsm_x4(uint32_t* r, uint32_t addr) {
    asm volatile("ldmatrix.sync.aligned.m8n8.x4.shared.b16 {%0,%1,%2,%3}, [%4];"
        : "=r"(r[0]), "=r"(r[1]), "=r"(r[2]), "=r"(r[3]) : "r"(addr));
}

__device__ __forceinline__ void split1(float a, uint16_t& h, uint16_t& l) {
    __nv_bfloat16 hb = __float2bfloat16_rn(a);
    float hf = __bfloat162float(hb);
    __nv_bfloat16 lb = __float2bfloat16_rn(a - hf);
    h = __bfloat16_as_ushort(hb);
    l = __bfloat16_as_ushort(lb);
}

__device__ __forceinline__ void mma16816(float* c, const uint32_t* a, uint32_t b0, uint32_t b1) {
    asm volatile("mma.sync.aligned.m16n8k16.row.col.f32.bf16.bf16.f32 "
        "{%0,%1,%2,%3}, {%4,%5,%6,%7}, {%8,%9}, {%0,%1,%2,%3};"
        : "+f"(c[0]), "+f"(c[1]), "+f"(c[2]), "+f"(c[3])
        : "r"(a[0]), "r"(a[1]), "r"(a[2]), "r"(a[3]), "r"(b0), "r"(b1));
}

// ---------------- prep kernels ----------------
__global__ void prep_x(const float* __restrict__ x) {
    size_t i = ((size_t)blockIdx.x * 256 + threadIdx.x) * 8;
    float4 a0 = *(const float4*)(x + i);
    float4 a1 = *(const float4*)(x + i + 4);
    uint16_t h[8], l[8];
    split1(a0.x, h[0], l[0]); split1(a0.y, h[1], l[1]);
    split1(a0.z, h[2], l[2]); split1(a0.w, h[3], l[3]);
    split1(a1.x, h[4], l[4]); split1(a1.y, h[5], l[5]);
    split1(a1.z, h[6], l[6]); split1(a1.w, h[7], l[7]);
    uint4 hw, lw;
    hw.x = h[0] | ((uint32_t)h[1] << 16); hw.y = h[2] | ((uint32_t)h[3] << 16);
    hw.z = h[4] | ((uint32_t)h[5] << 16); hw.w = h[6] | ((uint32_t)h[7] << 16);
    lw.x = l[0] | ((uint32_t)l[1] << 16); lw.y = l[2] | ((uint32_t)l[3] << 16);
    lw.z = l[4] | ((uint32_t)l[5] << 16); lw.w = l[6] | ((uint32_t)l[7] << 16);
    *(uint4*)(g_x_hi + i) = hw;
    *(uint4*)(g_x_lo + i) = lw;
}
__global__ void prep_wqkv(const float* __restrict__ w) {
    int k = blockIdx.x;          // 0..255
    int n = threadIdx.x;         // 0..767
    uint16_t h, l;
    split1(w[k * 768 + n], h, l);
    g_wq_hi[n * 256 + k] = __ushort_as_bfloat16(h);
    g_wq_lo[n * 256 + k] = __ushort_as_bfloat16(l);
}
__global__ void prep_wout(const float* __restrict__ w) {
    int k = blockIdx.x;          // 0..255
    int n = threadIdx.x;         // 0..255
    uint16_t h, l;
    split1(w[k * 256 + n], h, l);
    g_wo_hi[n * 256 + k] = __ushort_as_bfloat16(h);
    g_wo_lo[n * 256 + k] = __ushort_as_bfloat16(l);
}

// ---------------- pipelined split-bf16 GEMM via mma.sync ----------------
// C[Mt,Nt] = Ahi/lo[Mt,256] @ (Whi/lo[Nt,256])^T + bias
// CTA tile 128x256, 16 warps (4x4 grid, warp tile 32x64), K chunks of 32,
// 3-stage ring, ONE barrier per chunk, ldmatrix.x4 fragments.

#define LDA 40                        // bf16 stride: 8-row x 16B phases conflict-free
#define A_ARR (128 * LDA * 2)         // 10240 bytes
#define B_ARR (256 * LDA * 2)         // 20480 bytes
#define OFF_AHI 0
#define OFF_ALO A_ARR
#define OFF_BHI (2 * A_ARR)
#define OFF_BLO (2 * A_ARR + B_ARR)
#define STG_B (2 * A_ARR + 2 * B_ARR) // 61440 bytes per stage
#define SMO_BIAS (3 * STG_B)          // 184320
#define SMO_TOTAL (SMO_BIAS + 1024)   // 185344

__global__ __launch_bounds__(512, 1)
void gemm_mma(const __nv_bfloat16* __restrict__ Ahi,
              const __nv_bfloat16* __restrict__ Alo,
              const __nv_bfloat16* __restrict__ Bhi,
              const __nv_bfloat16* __restrict__ Blo,
              const float* __restrict__ bias,
              float* __restrict__ C,
              int Ntotal, int nN)
{
    extern __shared__ char smem[];
    float* sBias = (float*)(smem + SMO_BIAS);
    const uint32_t sb = smem_u32(smem);

    const int tid = threadIdx.x;
    const int m0 = (blockIdx.x / nN) * 128;
    const int n0 = (blockIdx.x % nN) * 256;
    const int wid = tid >> 5, lane = tid & 31;
    const int wm = wid & 3, wn = wid >> 2;      // 4 x 4 warp grid
    const int g = lane >> 2, tig = lane & 3;

    if (tid < 256) sBias[tid] = bias[n0 + tid];

    // staging coords (per chunk): A 1x16B, B 2x16B per thread per array
    const int sra = tid >> 2, sua = tid & 3;                 // A: 128 rows x 4 units
    const size_t goA = (size_t)(m0 + sra) * 256 + sua * 8;
    const uint32_t soA = (uint32_t)(sra * LDA + sua * 8) * 2;
    const int ub0 = tid * 2, ub1 = tid * 2 + 1;              // B: 256 rows x 4 units
    const int srb0 = ub0 >> 2, sub0 = ub0 & 3;
    const int srb1 = ub1 >> 2, sub1 = ub1 & 3;
    const size_t goB0 = (size_t)(n0 + srb0) * 256 + sub0 * 8;
    const size_t goB1 = (size_t)(n0 + srb1) * 256 + sub1 * 8;
    const uint32_t soB0 = (uint32_t)(srb0 * LDA + sub0 * 8) * 2;
    const uint32_t soB1 = (uint32_t)(srb1 * LDA + sub1 * 8) * 2;

    // ldmatrix lane address components
    const int lane15 = lane & 15;
    const int acol8 = (lane >> 4) * 8;                       // A: col +8 for lanes 16-31
    const uint32_t aoff = (uint32_t)((wm * 32 + lane15) * LDA + acol8) * 2;
    const int brow = (lane & 7) + ((lane & 16) ? 8 : 0);     // B: row within nf-pair
    const int bcol8 = (lane & 8) ? 8 : 0;
    const uint32_t boff = (uint32_t)((wn * 64 + brow) * LDA + bcol8) * 2;

    float c[2][8][4];
    #pragma unroll
    for (int mf = 0; mf < 2; mf++)
        #pragma unroll
        for (int nf = 0; nf < 8; nf++)
            #pragma unroll
            for (int j = 0; j < 4; j++) c[mf][nf][j] = 0.f;

    // ---- prologue: load chunks 0,1 into slots 0,1 ----
    #pragma unroll
    for (int pc = 0; pc < 2; pc++) {
        uint32_t st = sb + pc * STG_B;
        size_t ko = (size_t)pc * 32;
        cpasync16(st + OFF_AHI + soA, Ahi + goA + ko);
        cpasync16(st + OFF_ALO + soA, Alo + goA + ko);
        cpasync16(st + OFF_BHI + soB0, Bhi + goB0 + ko);
        cpasync16(st + OFF_BHI + soB1, Bhi + goB1 + ko);
        cpasync16(st + OFF_BLO + soB0, Blo + goB0 + ko);
        cpasync16(st + OFF_BLO + soB1, Blo + goB1 + ko);
        CP_COMMIT();
    }

    #pragma unroll 1
    for (int kc = 0; kc < 8; kc++) {
        CP_WAIT1();            // chunk kc resident (groups complete in commit order)
        __syncthreads();       // all see chunk kc; slot (kc+2)%3 readers done (iter kc-1)

        // issue chunk kc+2 into ring slot (kc+2)%3
        if (kc + 2 < 8) {
            uint32_t st = sb + ((kc + 2) % 3) * STG_B;
            size_t ko = (size_t)(kc + 2) * 32;
            cpasync16(st + OFF_AHI + soA, Ahi + goA + ko);
            cpasync16(st + OFF_ALO + soA, Alo + goA + ko);
            cpasync16(st + OFF_BHI + soB0, Bhi + goB0 + ko);
            cpasync16(st + OFF_BHI + soB1, Bhi + goB1 + ko);
            cpasync16(st + OFF_BLO + soB0, Blo + goB0 + ko);
            cpasync16(st + OFF_BLO + soB1, Blo + goB1 + ko);
        }
        CP_COMMIT();           // unconditional: keeps group positions aligned

        // ---- compute chunk kc ----
        const uint32_t stg = sb + (kc % 3) * STG_B;
        #pragma unroll
        for (int ks = 0; ks < 2; ks++) {
            const uint32_t ksb = stg + ks * 32;     // ks*16 cols * 2B
            uint32_t ah[2][4], al[2][4];
            #pragma unroll
            for (int mf = 0; mf < 2; mf++) {
                uint32_t aa = ksb + aoff + mf * (16 * LDA * 2);
                ldsm_x4(ah[mf], aa + OFF_AHI);
                ldsm_x4(al[mf], aa + OFF_ALO);
            }
            #pragma unroll
            for (int nfp = 0; nfp < 4; nfp++) {
                uint32_t ba = ksb + boff + nfp * (16 * LDA * 2);
                uint32_t bh[4], bl[4];
                ldsm_x4(bh, ba + OFF_BHI);
                ldsm_x4(bl, ba + OFF_BLO);
                #pragma unroll
                for (int mf = 0; mf < 2; mf++) {
                    mma16816(c[mf][2 * nfp],     ah[mf], bh[0], bh[1]);
                    mma16816(c[mf][2 * nfp],     ah[mf], bl[0], bl[1]);
                    mma16816(c[mf][2 * nfp],     al[mf], bh[0], bh[1]);
                    mma16816(c[mf][2 * nfp + 1], ah[mf], bh[2], bh[3]);
                    mma16816(c[mf][2 * nfp + 1], ah[mf], bl[2], bl[3]);
                    mma16816(c[mf][2 * nfp + 1], al[mf], bh[2], bh[3]);
                }
            }
        }
    }

    // ---- epilogue ----
    #pragma unroll
    for (int mf = 0; mf < 2; mf++) {
        int row0 = m0 + wm * 32 + mf * 16 + g;
        #pragma unroll
        for (int nf = 0; nf < 8; nf++) {
            int cl = wn * 64 + nf * 8 + tig * 2;
            float bx = sBias[cl], by = sBias[cl + 1];
            float2 v0 = make_float2(c[mf][nf][0] + bx, c[mf][nf][1] + by);
            float2 v1 = make_float2(c[mf][nf][2] + bx, c[mf][nf][3] + by);
            *(float2*)(C + (size_t)row0 * Ntotal + n0 + cl) = v0;
            *(float2*)(C + (size_t)(row0 + 8) * Ntotal + n0 + cl) = v1;
        }
    }
}

// ---------------- windowed attention (fp32) ----------------
#define AQS 34
#define AKT 52
#define ASS 50

__device__ __forceinline__ u64 splat2(float a) {
    u64 r; asm("mov.b64 %0, {%1, %1};" : "=l"(r) : "f"(a)); return r;
}
__device__ __forceinline__ float2 unpack2(u64 v) {
    float2 f; asm("mov.b64 {%0, %1}, %2;" : "=f"(f.x), "=f"(f.y) : "l"(v)); return f;
}
#define FMA2(d, a, b) asm("fma.rn.f32x2 %0, %1, %2, %0;" : "+l"(d) : "l"(a), "l"(b))

__global__ __launch_bounds__(256)
void attn_kernel(const float* __restrict__ qkv,
                 const float* __restrict__ pos,
                 __nv_bfloat16* __restrict__ Ohi,
                 __nv_bfloat16* __restrict__ Olo)
{
    __shared__ float Q[52 * AQS];
    __shared__ float KT[32 * AKT];
    __shared__ float V[49 * AQS];
    __shared__ float S[49 * ASS];
    __shared__ float POS[170];

    const int tid = threadIdx.x;
    const int win = blockIdx.x;
    const int b = win >> 6, wh = (win >> 3) & 7, ww = win & 7;
    const int ty = tid >> 4, tx = tid & 15;
    const int ty4 = ty * 4, dx = tx * 2;
    const float scl = 5.656854249492381f;   // sqrt(32)

    for (int i = tid; i < 169; i += 256) POS[i] = pos[i];
    const int rowbase = (b * 56 + wh * 7) * 56 + ww * 7;

    for (int h = 0; h < 8; h++) {
        __syncthreads();
        for (int q = tid; q < 784; q += 256) {
            int t = q >> 4, d2 = (q & 15) << 1;
            long row = rowbase + (t / 7) * 56 + (t % 7);
            const float* p = qkv + row * 768 + h * 32 + d2;
            float2 qv = *(const float2*)p;
            float2 kv = *(const float2*)(p + 256);
            float2 vv = *(const float2*)(p + 512);
            *(float2*)(Q + t * AQS + d2) = qv;
            KT[d2 * AKT + t] = kv.x;
            KT[(d2 + 1) * AKT + t] = kv.y;
            *(float2*)(V + t * AQS + d2) = vv;
        }
        __syncthreads();

        if (tid < 169) {
            int sy = tid / 13, sx = tid - sy * 13;
            int r0 = 4 * sy, c0 = 4 * sx;
            u64 sa[4][2];
            #pragma unroll
            for (int i = 0; i < 4; i++) { sa[i][0] = 0ULL; sa[i][1] = 0ULL; }
            #pragma unroll 4
            for (int d = 0; d < 32; d += 2) {
                u64 k0a = *(const u64*)(KT + d * AKT + c0);
                u64 k0b = *(const u64*)(KT + d * AKT + c0 + 2);
                u64 k1a = *(const u64*)(KT + (d + 1) * AKT + c0);
                u64 k1b = *(const u64*)(KT + (d + 1) * AKT + c0 + 2);
                #pragma unroll
                for (int i = 0; i < 4; i++) {
                    float2 qv = *(const float2*)(Q + (r0 + i) * AQS + d);
                    u64 qx = splat2(qv.x), qy = splat2(qv.y);
                    FMA2(sa[i][0], qx, k0a);
                    FMA2(sa[i][1], qx, k0b);
                    FMA2(sa[i][0], qy, k1a);
                    FMA2(sa[i][1], qy, k1b);
                }
            }
            #pragma unroll
            for (int i = 0; i < 4; i++) {
                int r = r0 + i;
                if (r < 49) {
                    int br = r / 7 + r % 7;
                    #pragma unroll
                    for (int jc = 0; jc < 2; jc++) {
                        int cc = c0 + 2 * jc;
                        if (cc <= 48) {
                            float2 f = unpack2(sa[i][jc]);
                            int bc0 = cc / 7 + cc % 7;
                            int bc1 = (cc + 1) / 7 + (cc + 1) % 7;
                            f.x = f.x * scl + POS[br * 13 + bc0];
                            f.y = f.y * scl + POS[br * 13 + bc1];
                            *(float2*)(S + r * ASS + cc) = f;
                        }
                    }
                }
            }
        }
        __syncthreads();

        {
            int warp = tid >> 5, lane = tid & 31;
            for (int r = warp; r < 49; r += 8) {
                float v0 = S[r * ASS + lane];
                float v1 = (lane + 32 < 49) ? S[r * ASS + lane + 32] : -3.0e38f;
                float m = fmaxf(v0, v1);
                #pragma unroll
                for (int off = 16; off > 0; off >>= 1)
                    m = fmaxf(m, __shfl_xor_sync(0xffffffffu, m, off));
                float e0 = __expf(v0 - m);
                float e1 = (lane + 32 < 49) ? __expf(v1 - m) : 0.f;
                float ss = e0 + e1;
                #pragma unroll
                for (int off = 16; off > 0; off >>= 1)
                    ss += __shfl_xor_sync(0xffffffffu, ss, off);
                float inv = 1.f / ss;
                S[r * ASS + lane] = e0 * inv;
                if (lane + 32 < 49) S[r * ASS + lane + 32] = e1 * inv;
            }
        }
        __syncthreads();

        {
            int rr[4];
            #pragma unroll
            for (int i = 0; i < 4; i++) rr[i] = (ty4 + i < 49) ? (ty4 + i) : 0;
            u64 o[4] = {0ULL, 0ULL, 0ULL, 0ULL};
            #pragma unroll 4
            for (int l = 0; l < 48; l += 2) {
                u64 v0 = *(const u64*)(V + l * AQS + dx);
                u64 v1 = *(const u64*)(V + (l + 1) * AQS + dx);
                #pragma unroll
                for (int i = 0; i < 4; i++) {
                    float2 sv = *(const float2*)(S + rr[i] * ASS + l);
                    FMA2(o[i], splat2(sv.x), v0);
                    FMA2(o[i], splat2(sv.y), v1);
                }
            }
            {
                u64 v48 = *(const u64*)(V + 48 * AQS + dx);
                #pragma unroll
                for (int i = 0; i < 4; i++)
                    FMA2(o[i], splat2(S[rr[i] * ASS + 48]), v48);
            }
            #pragma unroll
            for (int i = 0; i < 4; i++) {
                int row = ty4 + i;
                if (row < 49) {
                    long gr = rowbase + (row / 7) * 56 + (row % 7);
                    float2 v = unpack2(o[i]);
                    uint16_t h0, l0, h1, l1;
                    split1(v.x, h0, l0);
                    split1(v.y, h1, l1);
                    *(uint32_t*)(Ohi + gr * 256 + h * 32 + dx) = (uint32_t)h0 | ((uint32_t)h1 << 16);
                    *(uint32_t*)(Olo + gr * 256 + h * 32 + dx) = (uint32_t)l0 | ((uint32_t)l1 << 16);
                }
            }
        }
    }
}

// ---------------- host launcher ----------------
extern "C" void kernel_launch(void* const* d_in, const int* in_sizes, int n_in,
                              void* d_out, int out_size)
{
    const float* x    = (const float*)d_in[0];
    const float* pos  = (const float*)d_in[1];
    const float* wqkv = (const float*)d_in[2];
    const float* bqkv = (const float*)d_in[3];
    const float* wout = (const float*)d_in[4];
    const float* bout = (const float*)d_in[5];
    float* out = (float*)d_out;

    void *p_qkv, *p_xh, *p_xl, *p_oh, *p_ol, *p_wqh, *p_wql, *p_woh, *p_wol;
    cudaGetSymbolAddress(&p_qkv, g_qkv);
    cudaGetSymbolAddress(&p_xh, g_x_hi);
    cudaGetSymbolAddress(&p_xl, g_x_lo);
    cudaGetSymbolAddress(&p_oh, g_o_hi);
    cudaGetSymbolAddress(&p_ol, g_o_lo);
    cudaGetSymbolAddress(&p_wqh, g_wq_hi);
    cudaGetSymbolAddress(&p_wql, g_wq_lo);
    cudaGetSymbolAddress(&p_woh, g_wo_hi);
    cudaGetSymbolAddress(&p_wol, g_wo_lo);

    cudaFuncSetAttribute(gemm_mma, cudaFuncAttributeMaxDynamicSharedMemorySize, SMO_TOTAL);

    prep_x<<<M_TOTAL * 256 / (256 * 8), 256>>>(x);
    prep_wqkv<<<256, 768>>>(wqkv);
    prep_wout<<<256, 256>>>(wout);

    // GEMM1: qkv = x @ w_qkv + b_qkv   (M=200704, N=768)
    gemm_mma<<<(M_TOTAL / 128) * 3, 512, SMO_TOTAL>>>(
        (const __nv_bfloat16*)p_xh, (const __nv_bfloat16*)p_xl,
        (const __nv_bfloat16*)p_wqh, (const __nv_bfloat16*)p_wql,
        bqkv, (float*)p_qkv, 768, 3);

    // windowed attention
    attn_kernel<<<4096, 256>>>((const float*)p_qkv, pos,
                               (__nv_bfloat16*)p_oh, (__nv_bfloat16*)p_ol);

    // GEMM2: out = O @ w_out + b_out (M=200704, N=256)
    gemm_mma<<<(M_TOTAL / 128) * 1, 512, SMO_TOTAL>>>(
        (const __nv_bfloat16*)p_oh, (const __nv_bfloat16*)p_ol,
        (const __nv_bfloat16*)p_woh, (const __nv_bfloat16*)p_wol,
        bout, out, 256, 1);
}